// round 9
// baseline (speedup 1.0000x reference)
#include <cuda_runtime.h>
#include <cstdint>

#define N_TOTAL   100000
#define DIM       128
#define N_ENT     50000
#define RB        256                 // rows per block
#define BKT       16                  // rows per bucket (= per warp)
#define NBKT_ENT  (N_ENT / BKT)       // 3125
#define NBKT_TOT  (2 * NBKT_ENT)      // 6250
#define BLOCKS_ENT 196                // ceil(50000/256)
#define E_MAX     1700000

// Scratch (device globals)
__device__ unsigned g_wt[2][DIM * DIM];  // W in TF32, fragment-permuted [k][lq*16+n]
__device__ int  g_bcnt[NBKT_TOT];
__device__ int  g_boff[NBKT_TOT];
__device__ int  g_bcur[NBKT_TOT];
__device__ int2 g_edge[E_MAX];           // {col | (rowlow<<17), val_bits}

__device__ __forceinline__ unsigned cvt_tf32(float f) {
    unsigned r;
    asm("cvt.rna.tf32.f32 %0, %1;" : "=r"(r) : "f"(f));
    return r;
}

// ---------------------------------------------------------------------------
// 0) zero bucket counters
// ---------------------------------------------------------------------------
__global__ void zero_cnt_kernel() {
    int i = blockIdx.x * blockDim.x + threadIdx.x;
    if (i < NBKT_TOT) g_bcnt[i] = 0;
}

// ---------------------------------------------------------------------------
// 1) histogram of bucket ids
// ---------------------------------------------------------------------------
__global__ void hist_kernel(const int* __restrict__ rows_u,
                            const int* __restrict__ rows_i,
                            int E_u, int E_i) {
    int e = blockIdx.x * blockDim.x + threadIdx.x;
    if (e < E_u) {
        atomicAdd(&g_bcnt[__ldg(rows_u + e) >> 4], 1);
    } else {
        e -= E_u;
        if (e < E_i) atomicAdd(&g_bcnt[NBKT_ENT + (__ldg(rows_i + e) >> 4)], 1);
    }
}

// ---------------------------------------------------------------------------
// 2) exclusive scan over 6250 buckets (one block)
// ---------------------------------------------------------------------------
#define SCAN_THREADS 1024
#define SCAN_CHUNK   7               // 1024*7 = 7168 >= 6250
__global__ void scan_kernel() {
    __shared__ int sums[SCAN_THREADS];
    int t = threadIdx.x;
    int lo = t * SCAN_CHUNK;
    int hi = min(lo + SCAN_CHUNK, NBKT_TOT);

    int s = 0;
    for (int i = lo; i < hi; i++) s += g_bcnt[i];
    sums[t] = s;
    __syncthreads();

    for (int d = 1; d < SCAN_THREADS; d <<= 1) {
        int v = (t >= d) ? sums[t - d] : 0;
        __syncthreads();
        sums[t] += v;
        __syncthreads();
    }
    int run = (t == 0) ? 0 : sums[t - 1];

    for (int i = lo; i < hi; i++) {
        g_boff[i] = run;
        g_bcur[i] = run;
        run += g_bcnt[i];
    }
}

// ---------------------------------------------------------------------------
// 3) permute edges into bucket order, packing (col, row%16, val)
// ---------------------------------------------------------------------------
__global__ void permute_kernel(const int*   __restrict__ rows_u,
                               const int*   __restrict__ cols_u,
                               const float* __restrict__ vals_u,
                               const int*   __restrict__ rows_i,
                               const int*   __restrict__ cols_i,
                               const float* __restrict__ vals_i,
                               int E_u, int E_i) {
    int e = blockIdx.x * blockDim.x + threadIdx.x;
    int r, c, bid; float v;
    if (e < E_u) {
        r = __ldg(rows_u + e);
        c = __ldg(cols_u + e);
        v = __ldg(vals_u + e);
        bid = r >> 4;
    } else {
        e -= E_u;
        if (e >= E_i) return;
        r = __ldg(rows_i + e);
        c = __ldg(cols_i + e);
        v = __ldg(vals_i + e);
        bid = NBKT_ENT + (r >> 4);
    }
    int pos = atomicAdd(&g_bcur[bid], 1);
    g_edge[pos] = make_int2(c | ((r & 15) << 17), __float_as_int(v));
}

// ---------------------------------------------------------------------------
// 4) convert W to TF32, fragment-permuted: g_wt[e][k*128 + lq*16 + n]
//    = tf32(W[k][n*8 + lq])
// ---------------------------------------------------------------------------
__global__ void wconv_kernel(const float* __restrict__ Wu,
                             const float* __restrict__ Wi) {
    int i = blockIdx.x * blockDim.x + threadIdx.x;
    if (i < DIM * DIM) {
        int k = i >> 7, col = i & 127;
        int lq = col >> 4, n = col & 15;
        int src = k * DIM + n * 8 + lq;
        g_wt[0][i] = cvt_tf32(__ldg(Wu + src));
        g_wt[1][i] = cvt_tf32(__ldg(Wi + src));
    }
}

// ---------------------------------------------------------------------------
// 5) Fused: bucketed segment-sum (smem, atomic-free) + TF32 MMA GEMM + ReLU.
// Block = 256 rows, 512 threads (16 warps). Warp w owns bucket (16 rows).
// smem: As[256][132] fp32 accumulator (135168 B) then Ws[128][132] (67584 B).
// ---------------------------------------------------------------------------
#define AS_PITCH 132
#define AS_BYTES (RB * AS_PITCH * 4)
#define WS_BYTES (DIM * AS_PITCH * 4)
#define SMEM_TOTAL (AS_BYTES + WS_BYTES)

__global__ __launch_bounds__(512, 1)
void fused_kernel(const float* __restrict__ ebs, float* __restrict__ out) {
    extern __shared__ char smem[];
    float*    As  = reinterpret_cast<float*>(smem);                // [256][132]
    unsigned* Wsm = reinterpret_cast<unsigned*>(smem + AS_BYTES);  // [128][132]

    int b = blockIdx.x;
    int entity = (b >= BLOCKS_ENT) ? 1 : 0;
    int lbase = (b - entity * BLOCKS_ENT) * RB;    // entity-local row base

    int tid  = threadIdx.x;
    int w    = tid >> 5;
    int lane = tid & 31;

    // ---- stage W (already tf32 + permuted) into smem ----
    {
        const uint4* s4 = reinterpret_cast<const uint4*>(g_wt[entity]);
#pragma unroll
        for (int i = 0; i < 8; i++) {
            int u = tid + i * 512;                 // 4096 uint4 total
            uint4 v = s4[u];
            int idx = u * 4;
            *reinterpret_cast<uint4*>(&Wsm[(idx >> 7) * AS_PITCH + (idx & 127)]) = v;
        }
    }

    // ---- zero this warp's 16 accumulator rows ----
    int rbase_loc = w * BKT;
#pragma unroll
    for (int r = 0; r < BKT; r++)
        reinterpret_cast<float4*>(&As[(rbase_loc + r) * AS_PITCH])[lane] =
            make_float4(0.f, 0.f, 0.f, 0.f);

    // ---- accumulate bucket edges (warp-private, no atomics) ----
    {
        int lbkt = (lbase >> 4) + w;
        bool bvalid = (lbkt < NBKT_ENT);
        int gbkt = entity * NBKT_ENT + lbkt;
        int cnt   = bvalid ? g_bcnt[gbkt] : 0;
        int start = bvalid ? g_boff[gbkt] : 0;
        const int2* ep = g_edge + start;
        const float4* ebs4 = reinterpret_cast<const float4*>(ebs);

        int j = 0;
        for (; j + 4 <= cnt; j += 4) {
            int2 e0 = __ldg(ep + j);
            int2 e1 = __ldg(ep + j + 1);
            int2 e2 = __ldg(ep + j + 2);
            int2 e3 = __ldg(ep + j + 3);
            float4 gv0 = ebs4[(size_t)(e0.x & 0x1FFFF) * 32 + lane];
            float4 gv1 = ebs4[(size_t)(e1.x & 0x1FFFF) * 32 + lane];
            float4 gv2 = ebs4[(size_t)(e2.x & 0x1FFFF) * 32 + lane];
            float4 gv3 = ebs4[(size_t)(e3.x & 0x1FFFF) * 32 + lane];
#define UPD(E, G) { \
            int rr = (E).x >> 17; \
            float vv = __int_as_float((E).y); \
            float4* p = reinterpret_cast<float4*>(&As[(rbase_loc + rr) * AS_PITCH]) + lane; \
            float4 c = *p; \
            c.x = fmaf(vv, (G).x, c.x); c.y = fmaf(vv, (G).y, c.y); \
            c.z = fmaf(vv, (G).z, c.z); c.w = fmaf(vv, (G).w, c.w); \
            *p = c; }
            UPD(e0, gv0) UPD(e1, gv1) UPD(e2, gv2) UPD(e3, gv3)
        }
        for (; j < cnt; j++) {
            int2 e = __ldg(ep + j);
            float4 gv = ebs4[(size_t)(e.x & 0x1FFFF) * 32 + lane];
            UPD(e, gv)
        }
#undef UPD
    }

    __syncthreads();   // W staging visible to all; acc rows are warp-private

    // ---- TF32 MMA GEMM + ReLU ----
    int lq = lane >> 2;
    int lr = lane & 3;
    int rloc  = w * BKT + lq;
    int rloc2 = rloc + 8;
    int grow  = lbase + rloc;
    int grow2 = lbase + rloc2;
    bool va  = grow  < N_ENT;
    bool va2 = grow2 < N_ENT;
    float* O = out + (size_t)entity * N_ENT * DIM;

    float acc[16][4];
#pragma unroll
    for (int n = 0; n < 16; n++)
#pragma unroll
        for (int j = 0; j < 4; j++) acc[n][j] = 0.f;

#pragma unroll 1
    for (int ks = 0; ks < 16; ks++) {
        int k0 = ks * 8;
        unsigned a0 = cvt_tf32(As[rloc  * AS_PITCH + k0 + lr]);
        unsigned a1 = cvt_tf32(As[rloc2 * AS_PITCH + k0 + lr]);
        unsigned a2 = cvt_tf32(As[rloc  * AS_PITCH + k0 + 4 + lr]);
        unsigned a3 = cvt_tf32(As[rloc2 * AS_PITCH + k0 + 4 + lr]);

        uint4 b0q[4], b1q[4];
        {
            const uint4* w0 = reinterpret_cast<const uint4*>(&Wsm[(k0 + lr) * AS_PITCH + lq * 16]);
            const uint4* w1 = reinterpret_cast<const uint4*>(&Wsm[(k0 + 4 + lr) * AS_PITCH + lq * 16]);
#pragma unroll
            for (int j = 0; j < 4; j++) { b0q[j] = w0[j]; b1q[j] = w1[j]; }
        }
        const unsigned* bw0 = reinterpret_cast<const unsigned*>(b0q);
        const unsigned* bw1 = reinterpret_cast<const unsigned*>(b1q);

#pragma unroll
        for (int n = 0; n < 16; n++) {
            asm volatile(
                "mma.sync.aligned.m16n8k8.row.col.f32.tf32.tf32.f32 "
                "{%0,%1,%2,%3}, {%4,%5,%6,%7}, {%8,%9}, {%0,%1,%2,%3};\n"
                : "+f"(acc[n][0]), "+f"(acc[n][1]), "+f"(acc[n][2]), "+f"(acc[n][3])
                : "r"(a0), "r"(a1), "r"(a2), "r"(a3), "r"(bw0[n]), "r"(bw1[n]));
        }
    }

    // epilogue: ReLU + float2 stores
#pragma unroll
    for (int n = 0; n < 16; n++) {
        int col = n * 8 + lr * 2;
        if (va) {
            float2 o;
            o.x = fmaxf(acc[n][0], 0.f);
            o.y = fmaxf(acc[n][1], 0.f);
            *reinterpret_cast<float2*>(O + (size_t)grow * DIM + col) = o;
        }
        if (va2) {
            float2 o;
            o.x = fmaxf(acc[n][2], 0.f);
            o.y = fmaxf(acc[n][3], 0.f);
            *reinterpret_cast<float2*>(O + (size_t)grow2 * DIM + col) = o;
        }
    }
}

// ---------------------------------------------------------------------------
extern "C" void kernel_launch(void* const* d_in, const int* in_sizes, int n_in,
                              void* d_out, int out_size) {
    const float* ebs    = (const float*)d_in[0];
    const int*   rows_u = (const int*)  d_in[1];
    const int*   cols_u = (const int*)  d_in[2];
    const float* vals_u = (const float*)d_in[3];
    const float* W_u    = (const float*)d_in[4];
    const int*   rows_i = (const int*)  d_in[5];
    const int*   cols_i = (const int*)  d_in[6];
    const float* vals_i = (const float*)d_in[7];
    const float* W_i    = (const float*)d_in[8];
    float* out = (float*)d_out;

    int E_u = in_sizes[1];
    int E_i = in_sizes[5];
    int E_total = E_u + E_i;

    static bool attr_done = false;
    cudaFuncSetAttribute(fused_kernel,
                         cudaFuncAttributeMaxDynamicSharedMemorySize, SMEM_TOTAL);
    (void)attr_done;

    zero_cnt_kernel<<<(NBKT_TOT + 255) / 256, 256>>>();
    hist_kernel<<<(E_total + 255) / 256, 256>>>(rows_u, rows_i, E_u, E_i);
    scan_kernel<<<1, SCAN_THREADS>>>();
    permute_kernel<<<(E_total + 255) / 256, 256>>>(rows_u, cols_u, vals_u,
                                                   rows_i, cols_i, vals_i,
                                                   E_u, E_i);
    wconv_kernel<<<(DIM * DIM + 255) / 256, 256>>>(W_u, W_i);
    fused_kernel<<<2 * BLOCKS_ENT, 512, SMEM_TOTAL>>>(ebs, out);
}